// round 9
// baseline (speedup 1.0000x reference)
#include <cuda_runtime.h>
#include <cuda_bf16.h>
#include <cstdint>

#define N_NEURONS 65536
#define N_BKG     100
#define NSYN      5
#define NNZ       655360
#define SEQ_LEN   500
#define SPIKE_P   0.25f

#define OUT_ROW   (N_NEURONS * NSYN)   // 327680
#define NWORDS    16                   // ceil(500/32)
#define NBITW     (N_BKG * NWORDS)     // 1600
#define NBITW4    (NBITW / 4)          // 400 uint4

// ---------------- device scratch (no allocations allowed) ----------------
// g_count is zero at module load and re-zeroed by k_scan after use, so every
// replay sees zeros (determinism under graph replay).
__device__ int        g_count[N_NEURONS];
__device__ int        g_offs[N_NEURONS + 1];
__device__ int        g_cursor[N_NEURONS];
__device__ ulonglong2 g_ev4[NNZ];   // {pack(v0,v1), pack(v2,v3)}
__device__ float2     g_ev2[NNZ];   // {v4, col_as_float_bits}
__device__ unsigned   g_bits[NBITW];

// ---------------- prep kernels ----------------
// Fused: histogram + spike bitmask (independent work, one launch).
__global__ void k_hist_spike(const int* __restrict__ row_idx,
                             const float* __restrict__ noise) {
    int i = blockIdx.x * blockDim.x + threadIdx.x;
    if (i < NNZ) atomicAdd(&g_count[row_idx[i]], 1);
    if (i < NBITW) {
        int u  = i / NWORDS;
        int wi = i % NWORDS;
        unsigned w = 0;
        #pragma unroll 8
        for (int b = 0; b < 32; b++) {
            int t = wi * 32 + b;
            if (t < SEQ_LEN) {
                if (noise[(size_t)t * N_BKG + u] < SPIKE_P) w |= (1u << b);
            }
        }
        g_bits[u * NWORDS + wi] = w;
    }
}

// Two-level shuffle scan; re-zeros g_count after consuming it.
__global__ void k_scan() {
    __shared__ int wsum[32];
    int tid  = threadIdx.x;
    int lane = tid & 31;
    int wid  = tid >> 5;
    int base = tid * 64;

    int s = 0;
    #pragma unroll 4
    for (int i = 0; i < 64; i++) s += g_count[base + i];

    int v = s;
    #pragma unroll
    for (int d = 1; d < 32; d <<= 1) {
        int t = __shfl_up_sync(0xFFFFFFFFu, v, d);
        if (lane >= d) v += t;
    }
    if (lane == 31) wsum[wid] = v;
    __syncthreads();
    if (wid == 0) {
        int w = wsum[lane];
        #pragma unroll
        for (int d = 1; d < 32; d <<= 1) {
            int t = __shfl_up_sync(0xFFFFFFFFu, w, d);
            if (lane >= d) w += t;
        }
        wsum[lane] = w;
    }
    __syncthreads();

    int excl = v - s + (wid ? wsum[wid - 1] : 0);
    int run = excl;
    for (int i = 0; i < 64; i++) {
        int c = g_count[base + i];
        g_offs[base + i] = run;
        g_cursor[base + i] = run;
        run += c;
    }
    if (tid == 1023) g_offs[N_NEURONS] = run;
    // restore zeros for next replay (each thread zeros exactly what it read)
    for (int i = 0; i < 64; i++) g_count[base + i] = 0;
}

__global__ void k_scatter(const float* __restrict__ bw,
                          const float* __restrict__ factors,
                          const int* __restrict__ row_idx,
                          const int* __restrict__ col_idx) {
    int e = blockIdx.x * blockDim.x + threadIdx.x;
    if (e >= NNZ) return;
    int n = row_idx[e];
    int pos = atomicAdd(&g_cursor[n], 1);
    float w = bw[e];
    const float* f = factors + (size_t)e * NSYN;
    float v0 = w * f[0], v1 = w * f[1], v2 = w * f[2], v3 = w * f[3], v4 = w * f[4];
    ulonglong2 p;
    p.x = ((unsigned long long)__float_as_uint(v1) << 32) | __float_as_uint(v0);
    p.y = ((unsigned long long)__float_as_uint(v3) << 32) | __float_as_uint(v2);
    g_ev4[pos] = p;
    g_ev2[pos] = make_float2(v4, __int_as_float(col_idx[e]));
}

// ---------------- main kernel ----------------
// 8 passes x 2 t-groups (was 4x4): accumulator live set 10 regs instead of 20,
// total hot-loop live ~40 regs << 64-reg cap -> spill-proof with scheduling
// headroom (R7's 4x4 layout needed ~62 regs, right at the cap -> residual
// spills, the suspected cause of k_main ~420us vs ~150us model).
#define ECAP 512

__device__ __forceinline__ void acc_edge(unsigned wb,
                                         unsigned long long& a01,
                                         unsigned long long& a23,
                                         float& a4,
                                         const ulonglong2& v, float v4) {
    asm("{.reg .pred p;\n\t"
        "setp.ne.u32 p, %6, 0;\n\t"
        "@p add.rn.f32x2 %0, %0, %3;\n\t"
        "@p add.rn.f32x2 %1, %1, %4;\n\t"
        "@p add.f32 %2, %2, %5;}\n\t"
        : "+l"(a01), "+l"(a23), "+f"(a4)
        : "l"(v.x), "l"(v.y), "f"(v4), "r"(wb));
}

__global__ void __launch_bounds__(1024, 1)
k_main(float* __restrict__ out) {
    __shared__ ulonglong2 sE4[ECAP];
    __shared__ float2     sE2[ECAP];
    __shared__ uint2      sBits2[N_BKG * 8];  // [u*8 + pass] = words {2p, 2p+1}
    __shared__ float      sStage[32 * 161];   // 161 pad -> conflict-free

    int tid  = threadIdx.x;
    int wn   = tid >> 5;
    int lane = tid & 31;
    int n0   = blockIdx.x * 32;

    int base = g_offs[n0];
    int end  = g_offs[n0 + 32];
    int cnt  = min(end - base, ECAP);
    bool staged = (end - base) <= ECAP;

    for (int i = tid; i < cnt; i += 1024) {
        sE4[i] = g_ev4[base + i];
        sE2[i] = g_ev2[base + i];
    }
    {
        const uint4* gb4 = reinterpret_cast<const uint4*>(g_bits);
        uint4* sb4 = reinterpret_cast<uint4*>(sBits2);
        for (int i = tid; i < NBITW4; i += 1024) sb4[i] = gb4[i];
    }

    int n  = n0 + wn;
    int e0 = g_offs[n];
    int e1 = g_offs[n + 1];
    unsigned lm = 1u << lane;

    __syncthreads();

    for (int pass = 0; pass < 8; pass++) {
        unsigned long long a01[2] = {0ull, 0ull};
        unsigned long long a23[2] = {0ull, 0ull};
        float a4[2] = {0.f, 0.f};

        if (staged) {
            // branch-free smem-only path (common case)
            for (int l = e0 - base; l < e1 - base; ++l) {
                ulonglong2 v = sE4[l];
                float2 v2 = sE2[l];
                int u = __float_as_int(v2.y);
                uint2 b2 = sBits2[u * 8 + pass];           // LDS.64 broadcast
                acc_edge(b2.x & lm, a01[0], a23[0], a4[0], v, v2.x);
                acc_edge(b2.y & lm, a01[1], a23[1], a4[1], v, v2.x);
            }
        } else {
            // rare overflow fallback
            for (int e = e0; e < e1; ++e) {
                int l = e - base;
                ulonglong2 v; float2 v2;
                if (l < cnt) { v = sE4[l]; v2 = sE2[l]; }
                else         { v = g_ev4[e]; v2 = g_ev2[e]; }
                int u = __float_as_int(v2.y);
                uint2 b2 = sBits2[u * 8 + pass];
                acc_edge(b2.x & lm, a01[0], a23[0], a4[0], v, v2.x);
                acc_edge(b2.y & lm, a01[1], a23[1], a4[1], v, v2.x);
            }
        }

        // stage + coalesced store, one 32-t group at a time
        #pragma unroll
        for (int gi = 0; gi < 2; gi++) {
            int g = pass * 2 + gi;
            __syncthreads();  // stage buffer free
            {
                float f0 = __uint_as_float((unsigned)(a01[gi]));
                float f1 = __uint_as_float((unsigned)(a01[gi] >> 32));
                float f2 = __uint_as_float((unsigned)(a23[gi]));
                float f3 = __uint_as_float((unsigned)(a23[gi] >> 32));
                float* sp = &sStage[lane * 161 + wn * 5];
                sp[0] = f0; sp[1] = f1; sp[2] = f2; sp[3] = f3; sp[4] = a4[gi];
            }
            __syncthreads();
            int t = g * 32 + wn;          // warp wn stores t-row wn of this group
            if (t < SEQ_LEN) {
                float* op = out + (size_t)t * OUT_ROW + (size_t)n0 * 5;
                const float* sp = &sStage[wn * 161];
                #pragma unroll
                for (int k = lane; k < 160; k += 32) op[k] = sp[k];
            }
        }
    }
}

// ---------------- launcher ----------------
extern "C" void kernel_launch(void* const* d_in, const int* in_sizes, int n_in,
                              void* d_out, int out_size) {
    const float* noise   = (const float*)d_in[0];  // (1,500,100)
    const float* bw      = (const float*)d_in[1];  // (NNZ,)
    const float* factors = (const float*)d_in[2];  // (NNZ,5)
    const int*   row_idx = (const int*)d_in[3];    // (NNZ,)
    const int*   col_idx = (const int*)d_in[4];    // (NNZ,)
    float* out = (float*)d_out;

    // 4 launches (was 6): shifts the fixed ncu capture slot onto k_main.
    k_hist_spike<<<(NNZ + 255) / 256, 256>>>(row_idx, noise);
    k_scan<<<1, 1024>>>();
    k_scatter<<<(NNZ + 255) / 256, 256>>>(bw, factors, row_idx, col_idx);
    k_main<<<N_NEURONS / 32, 1024>>>(out);
}

// round 10
// speedup vs baseline: 1.0470x; 1.0470x over previous
#include <cuda_runtime.h>
#include <cuda_bf16.h>
#include <cstdint>

#define N_NEURONS 65536
#define N_BKG     100
#define NSYN      5
#define NNZ       655360
#define SEQ_LEN   500
#define SPIKE_P   0.25f

#define OUT_ROW   (N_NEURONS * NSYN)   // 327680
#define NWORDS    16                   // ceil(500/32)
#define NBITW     (N_BKG * NWORDS)     // 1600
#define NBITW4    (NBITW / 4)          // 400 uint4

// ---------------- device scratch (no allocations allowed) ----------------
// g_count is zero at module load and re-zeroed by k_scan after use, so every
// replay sees zeros (determinism under graph replay).
__device__ int        g_count[N_NEURONS];
__device__ int        g_offs[N_NEURONS + 1];
__device__ int        g_cursor[N_NEURONS];
__device__ ulonglong2 g_ev4[NNZ];   // {pack(v0,v1), pack(v2,v3)}
__device__ float2     g_ev2[NNZ];   // {v4, (col*4)_as_float_bits}
__device__ unsigned   g_bits[NBITW];

// ---------------- prep kernels ----------------
// Fused: histogram + spike bitmask (independent work, one launch).
__global__ void k_hist_spike(const int* __restrict__ row_idx,
                             const float* __restrict__ noise) {
    int i = blockIdx.x * blockDim.x + threadIdx.x;
    if (i < NNZ) atomicAdd(&g_count[row_idx[i]], 1);
    if (i < NBITW) {
        int u  = i / NWORDS;
        int wi = i % NWORDS;
        unsigned w = 0;
        #pragma unroll 8
        for (int b = 0; b < 32; b++) {
            int t = wi * 32 + b;
            if (t < SEQ_LEN) {
                if (noise[(size_t)t * N_BKG + u] < SPIKE_P) w |= (1u << b);
            }
        }
        g_bits[u * NWORDS + wi] = w;
    }
}

// Two-level shuffle scan; re-zeros g_count after consuming it.
__global__ void k_scan() {
    __shared__ int wsum[32];
    int tid  = threadIdx.x;
    int lane = tid & 31;
    int wid  = tid >> 5;
    int base = tid * 64;

    int s = 0;
    #pragma unroll 4
    for (int i = 0; i < 64; i++) s += g_count[base + i];

    int v = s;
    #pragma unroll
    for (int d = 1; d < 32; d <<= 1) {
        int t = __shfl_up_sync(0xFFFFFFFFu, v, d);
        if (lane >= d) v += t;
    }
    if (lane == 31) wsum[wid] = v;
    __syncthreads();
    if (wid == 0) {
        int w = wsum[lane];
        #pragma unroll
        for (int d = 1; d < 32; d <<= 1) {
            int t = __shfl_up_sync(0xFFFFFFFFu, w, d);
            if (lane >= d) w += t;
        }
        wsum[lane] = w;
    }
    __syncthreads();

    int excl = v - s + (wid ? wsum[wid - 1] : 0);
    int run = excl;
    for (int i = 0; i < 64; i++) {
        int c = g_count[base + i];
        g_offs[base + i] = run;
        g_cursor[base + i] = run;
        run += c;
    }
    if (tid == 1023) g_offs[N_NEURONS] = run;
    for (int i = 0; i < 64; i++) g_count[base + i] = 0;
}

__global__ void k_scatter(const float* __restrict__ bw,
                          const float* __restrict__ factors,
                          const int* __restrict__ row_idx,
                          const int* __restrict__ col_idx) {
    int e = blockIdx.x * blockDim.x + threadIdx.x;
    if (e >= NNZ) return;
    int n = row_idx[e];
    int pos = atomicAdd(&g_cursor[n], 1);
    float w = bw[e];
    const float* f = factors + (size_t)e * NSYN;
    float v0 = w * f[0], v1 = w * f[1], v2 = w * f[2], v3 = w * f[3], v4 = w * f[4];
    ulonglong2 p;
    p.x = ((unsigned long long)__float_as_uint(v1) << 32) | __float_as_uint(v0);
    p.y = ((unsigned long long)__float_as_uint(v3) << 32) | __float_as_uint(v2);
    g_ev4[pos] = p;
    // pre-scale col by 4: saves one IMAD per edge-pass in the hot loop
    g_ev2[pos] = make_float2(v4, __int_as_float(col_idx[e] * 4));
}

// ---------------- main kernel ----------------
// 4 passes x 4 t-groups (fixed-reg version of R7's layout): per-edge fixed
// cost (payload LDS + loop) and barrier convoy paid 4x instead of 8x.
// Reg diet vs R7: AND folded into asm (no live wb[4]), col pre-scaled (no
// IMAD), staged/fallback loop split (no per-edge bounds check). Live ~44
// regs <= 64 cap with ~20 regs of pipelining headroom (R9's 8x2 showed
// ptxas fills to cap productively when given slack).
#define ECAP 512

__device__ __forceinline__ void acc_edge(unsigned word, unsigned lm,
                                         unsigned long long& a01,
                                         unsigned long long& a23,
                                         float& a4,
                                         unsigned long long vx,
                                         unsigned long long vy, float v4) {
    asm("{.reg .pred p; .reg .b32 t;\n\t"
        "and.b32 t, %6, %7;\n\t"
        "setp.ne.u32 p, t, 0;\n\t"
        "@p add.rn.f32x2 %0, %0, %3;\n\t"
        "@p add.rn.f32x2 %1, %1, %4;\n\t"
        "@p add.f32 %2, %2, %5;}\n\t"
        : "+l"(a01), "+l"(a23), "+f"(a4)
        : "l"(vx), "l"(vy), "f"(v4), "r"(word), "r"(lm));
}

__global__ void __launch_bounds__(1024, 1)
k_main(float* __restrict__ out) {
    __shared__ ulonglong2 sE4[ECAP];
    __shared__ float2     sE2[ECAP];
    __shared__ uint4      sBits4[NBITW4];     // [u*4 + pass]
    __shared__ float      sStage[32 * 161];   // 161 pad -> conflict-free

    int tid  = threadIdx.x;
    int wn   = tid >> 5;
    int lane = tid & 31;
    int n0   = blockIdx.x * 32;

    int base = g_offs[n0];
    int end  = g_offs[n0 + 32];
    int cnt  = min(end - base, ECAP);
    bool staged = (end - base) <= ECAP;

    for (int i = tid; i < cnt; i += 1024) {
        sE4[i] = g_ev4[base + i];
        sE2[i] = g_ev2[base + i];
    }
    {
        const uint4* gb4 = reinterpret_cast<const uint4*>(g_bits);
        for (int i = tid; i < NBITW4; i += 1024) sBits4[i] = gb4[i];
    }

    int n  = n0 + wn;
    int e0 = g_offs[n];
    int e1 = g_offs[n + 1];
    unsigned lm = 1u << lane;

    __syncthreads();

    for (int pass = 0; pass < 4; pass++) {
        unsigned long long a01[4] = {0ull, 0ull, 0ull, 0ull};
        unsigned long long a23[4] = {0ull, 0ull, 0ull, 0ull};
        float a4[4] = {0.f, 0.f, 0.f, 0.f};

        if (staged) {
            // branch-free smem-only path (overwhelmingly common case)
            for (int l = e0 - base; l < e1 - base; ++l) {
                ulonglong2 v = sE4[l];
                float2 v2 = sE2[l];
                int u4 = __float_as_int(v2.y);                 // col*4
                uint4 b = sBits4[u4 + pass];                   // one LDS.128 broadcast
                acc_edge(b.x, lm, a01[0], a23[0], a4[0], v.x, v.y, v2.x);
                acc_edge(b.y, lm, a01[1], a23[1], a4[1], v.x, v.y, v2.x);
                acc_edge(b.z, lm, a01[2], a23[2], a4[2], v.x, v.y, v2.x);
                acc_edge(b.w, lm, a01[3], a23[3], a4[3], v.x, v.y, v2.x);
            }
        } else {
            // rare overflow fallback
            for (int e = e0; e < e1; ++e) {
                int l = e - base;
                ulonglong2 v; float2 v2;
                if (l < cnt) { v = sE4[l]; v2 = sE2[l]; }
                else         { v = g_ev4[e]; v2 = g_ev2[e]; }
                int u4 = __float_as_int(v2.y);
                uint4 b = sBits4[u4 + pass];
                acc_edge(b.x, lm, a01[0], a23[0], a4[0], v.x, v.y, v2.x);
                acc_edge(b.y, lm, a01[1], a23[1], a4[1], v.x, v.y, v2.x);
                acc_edge(b.z, lm, a01[2], a23[2], a4[2], v.x, v.y, v2.x);
                acc_edge(b.w, lm, a01[3], a23[3], a4[3], v.x, v.y, v2.x);
            }
        }

        // stage + coalesced store, one 32-t group at a time
        #pragma unroll
        for (int gi = 0; gi < 4; gi++) {
            int g = pass * 4 + gi;
            __syncthreads();  // stage buffer free
            {
                float f0 = __uint_as_float((unsigned)(a01[gi]));
                float f1 = __uint_as_float((unsigned)(a01[gi] >> 32));
                float f2 = __uint_as_float((unsigned)(a23[gi]));
                float f3 = __uint_as_float((unsigned)(a23[gi] >> 32));
                float* sp = &sStage[lane * 161 + wn * 5];
                sp[0] = f0; sp[1] = f1; sp[2] = f2; sp[3] = f3; sp[4] = a4[gi];
            }
            __syncthreads();
            int t = g * 32 + wn;          // warp wn stores t-row wn of this group
            if (t < SEQ_LEN) {
                float* op = out + (size_t)t * OUT_ROW + (size_t)n0 * 5;
                const float* sp = &sStage[wn * 161];
                #pragma unroll
                for (int k = lane; k < 160; k += 32) op[k] = sp[k];
            }
        }
    }
}

// ---------------- launcher ----------------
extern "C" void kernel_launch(void* const* d_in, const int* in_sizes, int n_in,
                              void* d_out, int out_size) {
    const float* noise   = (const float*)d_in[0];  // (1,500,100)
    const float* bw      = (const float*)d_in[1];  // (NNZ,)
    const float* factors = (const float*)d_in[2];  // (NNZ,5)
    const int*   row_idx = (const int*)d_in[3];    // (NNZ,)
    const int*   col_idx = (const int*)d_in[4];    // (NNZ,)
    float* out = (float*)d_out;

    k_hist_spike<<<(NNZ + 255) / 256, 256>>>(row_idx, noise);
    k_scan<<<1, 1024>>>();
    k_scatter<<<(NNZ + 255) / 256, 256>>>(bw, factors, row_idx, col_idx);
    k_main<<<N_NEURONS / 32, 1024>>>(out);
}

// round 17
// speedup vs baseline: 1.1499x; 1.0983x over previous
#include <cuda_runtime.h>
#include <cuda_bf16.h>
#include <cstdint>

#define N_NEURONS 65536
#define N_BKG     100
#define NSYN      5
#define NNZ       655360
#define SEQ_LEN   500
#define SPIKE_P   0.25f

#define OUT_ROW   (N_NEURONS * NSYN)   // 327680
#define NWORDS    16                   // ceil(500/32)
#define NBITW     (N_BKG * NWORDS)     // 1600
#define NBITW4    (NBITW / 4)          // 400 uint4

// ---------------- device scratch (no allocations allowed) ----------------
__device__ int        g_count[N_NEURONS];
__device__ int        g_offs[N_NEURONS + 1];
__device__ int        g_cursor[N_NEURONS];
__device__ ulonglong2 g_ev4[NNZ];   // {pack(v0,v1), pack(v2,v3)}
__device__ float2     g_ev2[NNZ];   // {v4, (col*4)_as_float_bits}
__device__ unsigned   g_bits[NBITW];

// ---------------- prep kernels (unchanged from R10) ----------------
__global__ void k_hist_spike(const int* __restrict__ row_idx,
                             const float* __restrict__ noise) {
    int i = blockIdx.x * blockDim.x + threadIdx.x;
    if (i < NNZ) atomicAdd(&g_count[row_idx[i]], 1);
    if (i < NBITW) {
        int u  = i / NWORDS;
        int wi = i % NWORDS;
        unsigned w = 0;
        #pragma unroll 8
        for (int b = 0; b < 32; b++) {
            int t = wi * 32 + b;
            if (t < SEQ_LEN) {
                if (noise[(size_t)t * N_BKG + u] < SPIKE_P) w |= (1u << b);
            }
        }
        g_bits[u * NWORDS + wi] = w;
    }
}

__global__ void k_scan() {
    __shared__ int wsum[32];
    int tid  = threadIdx.x;
    int lane = tid & 31;
    int wid  = tid >> 5;
    int base = tid * 64;

    int s = 0;
    #pragma unroll 4
    for (int i = 0; i < 64; i++) s += g_count[base + i];

    int v = s;
    #pragma unroll
    for (int d = 1; d < 32; d <<= 1) {
        int t = __shfl_up_sync(0xFFFFFFFFu, v, d);
        if (lane >= d) v += t;
    }
    if (lane == 31) wsum[wid] = v;
    __syncthreads();
    if (wid == 0) {
        int w = wsum[lane];
        #pragma unroll
        for (int d = 1; d < 32; d <<= 1) {
            int t = __shfl_up_sync(0xFFFFFFFFu, w, d);
            if (lane >= d) w += t;
        }
        wsum[lane] = w;
    }
    __syncthreads();

    int excl = v - s + (wid ? wsum[wid - 1] : 0);
    int run = excl;
    for (int i = 0; i < 64; i++) {
        int c = g_count[base + i];
        g_offs[base + i] = run;
        g_cursor[base + i] = run;
        run += c;
    }
    if (tid == 1023) g_offs[N_NEURONS] = run;
    for (int i = 0; i < 64; i++) g_count[base + i] = 0;
}

__global__ void k_scatter(const float* __restrict__ bw,
                          const float* __restrict__ factors,
                          const int* __restrict__ row_idx,
                          const int* __restrict__ col_idx) {
    int e = blockIdx.x * blockDim.x + threadIdx.x;
    if (e >= NNZ) return;
    int n = row_idx[e];
    int pos = atomicAdd(&g_cursor[n], 1);
    float w = bw[e];
    const float* f = factors + (size_t)e * NSYN;
    float v0 = w * f[0], v1 = w * f[1], v2 = w * f[2], v3 = w * f[3], v4 = w * f[4];
    ulonglong2 p;
    p.x = ((unsigned long long)__float_as_uint(v1) << 32) | __float_as_uint(v0);
    p.y = ((unsigned long long)__float_as_uint(v3) << 32) | __float_as_uint(v2);
    g_ev4[pos] = p;
    g_ev2[pos] = make_float2(v4, __int_as_float(col_idx[e] * 4));
}

// ---------------- main kernel ----------------
// 512 threads = 16 warps = 16 neurons/CTA, 2 CTAs/SM (512*64regs*2 = full RF).
// Same 32 warps/SM as before, but barriers sync only 16 warps: while one CTA
// convoys at a barrier, the co-resident CTA issues -> targets the 50% idle
// issue slots seen in R9/R10. Syncs cut 32 -> 16 via 2-group staging.
// Edge loop identical to R10 (4 passes x 4 t-groups, ~44 live regs).
#define NWARP  16
#define ECAP   320   // 16 neurons: mean 160, sigma ~12.6 -> +12.7 sigma

__device__ __forceinline__ void acc_edge(unsigned word, unsigned lm,
                                         unsigned long long& a01,
                                         unsigned long long& a23,
                                         float& a4,
                                         unsigned long long vx,
                                         unsigned long long vy, float v4) {
    asm("{.reg .pred p; .reg .b32 t;\n\t"
        "and.b32 t, %6, %7;\n\t"
        "setp.ne.u32 p, t, 0;\n\t"
        "@p add.rn.f32x2 %0, %0, %3;\n\t"
        "@p add.rn.f32x2 %1, %1, %4;\n\t"
        "@p add.f32 %2, %2, %5;}\n\t"
        : "+l"(a01), "+l"(a23), "+f"(a4)
        : "l"(vx), "l"(vy), "f"(v4), "r"(word), "r"(lm));
}

__global__ void __launch_bounds__(512, 2)
k_main(float* __restrict__ out) {
    __shared__ ulonglong2 sE4[ECAP];                 // 5.0 KB
    __shared__ float2     sE2[ECAP];                 // 2.5 KB
    __shared__ uint4      sBits4[NBITW4];            // 6.4 KB  [u*4 + pass]
    __shared__ float      sStage[64 * 81];           // 20.7 KB; 81 pad (odd) -> conflict-free

    int tid  = threadIdx.x;
    int wn   = tid >> 5;          // 0..15 : neuron within CTA
    int lane = tid & 31;          // t within 32-t group
    int n0   = blockIdx.x * NWARP;

    int base = g_offs[n0];
    int end  = g_offs[n0 + NWARP];
    int cnt  = min(end - base, ECAP);
    bool staged = (end - base) <= ECAP;

    for (int i = tid; i < cnt; i += 512) {
        sE4[i] = g_ev4[base + i];
        sE2[i] = g_ev2[base + i];
    }
    {
        const uint4* gb4 = reinterpret_cast<const uint4*>(g_bits);
        for (int i = tid; i < NBITW4; i += 512) sBits4[i] = gb4[i];
    }

    int n  = n0 + wn;
    int e0 = g_offs[n];
    int e1 = g_offs[n + 1];
    unsigned lm = 1u << lane;

    __syncthreads();

    for (int pass = 0; pass < 4; pass++) {
        unsigned long long a01[4] = {0ull, 0ull, 0ull, 0ull};
        unsigned long long a23[4] = {0ull, 0ull, 0ull, 0ull};
        float a4[4] = {0.f, 0.f, 0.f, 0.f};

        if (staged) {
            for (int l = e0 - base; l < e1 - base; ++l) {
                ulonglong2 v = sE4[l];
                float2 v2 = sE2[l];
                int u4 = __float_as_int(v2.y);                 // col*4
                uint4 b = sBits4[u4 + pass];                   // one LDS.128 broadcast
                acc_edge(b.x, lm, a01[0], a23[0], a4[0], v.x, v.y, v2.x);
                acc_edge(b.y, lm, a01[1], a23[1], a4[1], v.x, v.y, v2.x);
                acc_edge(b.z, lm, a01[2], a23[2], a4[2], v.x, v.y, v2.x);
                acc_edge(b.w, lm, a01[3], a23[3], a4[3], v.x, v.y, v2.x);
            }
        } else {
            for (int e = e0; e < e1; ++e) {
                int l = e - base;
                ulonglong2 v; float2 v2;
                if (l < cnt) { v = sE4[l]; v2 = sE2[l]; }
                else         { v = g_ev4[e]; v2 = g_ev2[e]; }
                int u4 = __float_as_int(v2.y);
                uint4 b = sBits4[u4 + pass];
                acc_edge(b.x, lm, a01[0], a23[0], a4[0], v.x, v.y, v2.x);
                acc_edge(b.y, lm, a01[1], a23[1], a4[1], v.x, v.y, v2.x);
                acc_edge(b.z, lm, a01[2], a23[2], a4[2], v.x, v.y, v2.x);
                acc_edge(b.w, lm, a01[3], a23[3], a4[3], v.x, v.y, v2.x);
            }
        }

        // stage + store, TWO 32-t groups per barrier pair (16 syncs total)
        #pragma unroll
        for (int h = 0; h < 2; h++) {
            __syncthreads();   // stage buffer free (prev reads done)
            #pragma unroll
            for (int gl = 0; gl < 2; gl++) {
                int gi = h * 2 + gl;
                float* sp = &sStage[(gl * 32 + lane) * 81 + wn * 5];
                sp[0] = __uint_as_float((unsigned)(a01[gi]));
                sp[1] = __uint_as_float((unsigned)(a01[gi] >> 32));
                sp[2] = __uint_as_float((unsigned)(a23[gi]));
                sp[3] = __uint_as_float((unsigned)(a23[gi] >> 32));
                sp[4] = a4[gi];
            }
            __syncthreads();   // stage filled
            // 64 t-rows, 16 warps -> 4 rows/warp; row = 80 contiguous floats
            #pragma unroll
            for (int rr = 0; rr < 4; rr++) {
                int r = rr * NWARP + wn;
                int t = pass * 128 + h * 64 + r;
                if (t < SEQ_LEN) {
                    float* op = out + (size_t)t * OUT_ROW + (size_t)n0 * 5;
                    const float* sp = &sStage[r * 81];
                    #pragma unroll
                    for (int k = lane; k < 80; k += 32) op[k] = sp[k];
                }
            }
        }
    }
}

// ---------------- launcher ----------------
extern "C" void kernel_launch(void* const* d_in, const int* in_sizes, int n_in,
                              void* d_out, int out_size) {
    const float* noise   = (const float*)d_in[0];  // (1,500,100)
    const float* bw      = (const float*)d_in[1];  // (NNZ,)
    const float* factors = (const float*)d_in[2];  // (NNZ,5)
    const int*   row_idx = (const int*)d_in[3];    // (NNZ,)
    const int*   col_idx = (const int*)d_in[4];    // (NNZ,)
    float* out = (float*)d_out;

    k_hist_spike<<<(NNZ + 255) / 256, 256>>>(row_idx, noise);
    k_scan<<<1, 1024>>>();
    k_scatter<<<(NNZ + 255) / 256, 256>>>(bw, factors, row_idx, col_idx);
    k_main<<<N_NEURONS / NWARP, 512>>>(out);
}